// round 7
// baseline (speedup 1.0000x reference)
#include <cuda_runtime.h>

#define FULL_MASK 0xffffffffu
typedef unsigned long long u64;

// ---- f32x2 packed helpers (sm_103a FFMA2 only reachable via PTX) ----
__device__ __forceinline__ u64 pk(float lo, float hi) {
    u64 r; asm("mov.b64 %0,{%1,%2};" : "=l"(r) : "f"(lo), "f"(hi)); return r;
}
__device__ __forceinline__ void up(u64 v, float& lo, float& hi) {
    asm("mov.b64 {%0,%1},%2;" : "=f"(lo), "=f"(hi) : "l"(v));
}
__device__ __forceinline__ u64 f2fma(u64 a, u64 b, u64 c) {
    u64 d; asm("fma.rn.f32x2 %0,%1,%2,%3;" : "=l"(d) : "l"(a), "l"(b), "l"(c)); return d;
}
__device__ __forceinline__ u64 f2mul(u64 a, u64 b) {
    u64 d; asm("mul.rn.f32x2 %0,%1,%2;" : "=l"(d) : "l"(a), "l"(b)); return d;
}
__device__ __forceinline__ u64 swp(u64 v) {
    float a, b; up(v, a, b); return pk(b, a);
}

// ============================================================================
// Layouts (half-warp sl = lane&15 owns one sample; 32 amps/lane = 16 packs).
// Phase A:  amp i = (p<<5)|(h<<4)|sl   (p = pack 0..15, h = in-pack half)
//           i bits 8..5 = p, bit 4 = h, bits 3..0 = sl
// Phase B:  k' = (i bit8 <<4)|(i bits 3..0), sl' = i bits 7..4
//           pack p' = k'>>1, half h' = k' bit0 (= i bit 0)
// Shared buffer phys addr = logical ^ ((logical>>4)&15)  (conflict-free on
// the deterministic store/load sides).
// Qubit w <-> index bit 8-w.
// ============================================================================

// Gate on pack bit PB (16 packs), coefficients broadcast; m10=-conj(m01), m11=conj(m00).
template <int PB>
__device__ __forceinline__ void gate16(u64 (&R)[16], u64 (&I)[16],
                                       float2 m00, float2 m01) {
    const u64 c00x = pk(m00.x, m00.x), c00y = pk(m00.y, m00.y);
    const u64 c01x = pk(m01.x, m01.x), c01y = pk(m01.y, m01.y);
    const u64 n00y = pk(-m00.y, -m00.y), n01x = pk(-m01.x, -m01.x);
    const u64 n01y = pk(-m01.y, -m01.y);
    const int d = 1 << PB;
#pragma unroll
    for (int t = 0; t < 8; t++) {
        const int q = ((t >> PB) << (PB + 1)) | (t & (d - 1));
        const int j = q | d;
        u64 A = R[q], Ai = I[q], Bv = R[j], Bi = I[j];
        R[q] = f2fma(c00x, A,  f2fma(n00y, Ai, f2fma(c01x, Bv, f2mul(n01y, Bi))));
        I[q] = f2fma(c00x, Ai, f2fma(c00y, A,  f2fma(c01x, Bi, f2mul(c01y, Bv))));
        R[j] = f2fma(n01x, A,  f2fma(n01y, Ai, f2fma(c00x, Bv, f2mul(c00y, Bi))));
        I[j] = f2fma(n01x, Ai, f2fma(c01y, A,  f2fma(c00x, Bi, f2mul(n00y, Bv))));
    }
}

// Gate on the in-pack bit (lo half = |0>, hi half = |1>).
__device__ __forceinline__ void gate16_in(u64 (&R)[16], u64 (&I)[16],
                                          float2 m00, float2 m01) {
    const u64 c00x = pk(m00.x, m00.x);
    const u64 cA = pk(-m00.y,  m00.y);
    const u64 cB = pk( m00.y, -m00.y);
    const u64 cC = pk( m01.x, -m01.x);
    const u64 cD = pk(-m01.y, -m01.y);
    const u64 cE = pk( m01.y,  m01.y);
#pragma unroll
    for (int p = 0; p < 16; p++) {
        u64 sR = swp(R[p]), sI = swp(I[p]);
        u64 Rn = f2fma(c00x, R[p], f2fma(cA, I[p], f2fma(cC, sR, f2mul(cD, sI))));
        u64 In = f2fma(c00x, I[p], f2fma(cB, R[p], f2fma(cC, sI, f2mul(cE, sR))));
        R[p] = Rn; I[p] = In;
    }
}

__global__ void __launch_bounds__(128, 4)
qsim_kernel(const float* __restrict__ x, const float* __restrict__ wt,
            float* __restrict__ out, int B) {
    __shared__ float2 s_m00[27];
    __shared__ float2 s_m01[27];
    __shared__ unsigned short s_perm[3 * 512];   // pre-swizzled phase-A dest
    __shared__ float2 s_buf[8][512];             // one 4KB buffer per half-warp

    const int tid = threadIdx.x;

    // ---- 27 rotation matrices (m00, m01; m10/m11 derived) ----
    if (tid < 27) {
        const float* p = wt + tid * 3;
        float phi = p[0], th = p[1], om = p[2];
        float a  = 0.5f * (phi + om);
        float bb = 0.5f * (phi - om);
        float c = cosf(0.5f * th), s = sinf(0.5f * th);
        float ca = cosf(a),  sa = sinf(a);
        float cb = cosf(bb), sb = sinf(bb);
        s_m00[tid] = make_float2(c * ca, -c * sa);
        s_m01[tid] = make_float2(-s * cb, -s * sb);
    }
    // ---- CNOT-ring permutations, with phase-A phys swizzle folded in ----
    for (int i2 = tid; i2 < 3 * 512; i2 += blockDim.x) {
        int l = i2 >> 9, idx = i2 & 511, r = l + 1;
        int v = idx;
#pragma unroll
        for (int g = 0; g < 9; g++) {
            int pc = 8 - g;
            int t = g + r; if (t >= 9) t -= 9;
            int pt = 8 - t;
            v ^= ((v >> pc) & 1) << pt;
        }
        s_perm[i2] = (unsigned short)(v ^ ((v >> 4) & 15));
    }
    __syncthreads();

    const int lane = tid & 31;
    const int sl = lane & 15;
    const int hl = (lane >> 4) & 1;
    const int warp = tid >> 5;
    float2* buf = s_buf[warp * 2 + hl];
    const int wg = blockIdx.x * 4 + warp;
    const int nw = gridDim.x * 4;
    const int npair = B >> 1;

    for (int pair = wg; pair < npair; pair += nw) {
        const int b = pair * 2 + hl;

        // ---- initial separable state ----
        float cs[9], sn[9];
#pragma unroll
        for (int w = 0; w < 9; w++) {
            float h2 = 0.5f * __ldg(&x[b * 9 + w]);
            __sincosf(h2, &sn[w], &cs[w]);
        }
        float lf = 1.0f;                        // lane factor: bits 3..0 -> qubits 8..5
#pragma unroll
        for (int q = 0; q < 4; q++)
            lf *= ((sl >> q) & 1) ? sn[8 - q] : cs[8 - q];
        const int spc = __popc(sl);

        u64 R[16], I[16];
#pragma unroll
        for (int p = 0; p < 16; p++) {
            float pf = lf;                      // p bits 0..3 -> qubits 3..0
#pragma unroll
            for (int q = 0; q < 4; q++)
                pf *= ((p >> q) & 1) ? sn[3 - q] : cs[3 - q];
            float rr[2], ii[2];
#pragma unroll
            for (int h = 0; h < 2; h++) {       // h -> qubit 4
                float f = pf * (h ? sn[4] : cs[4]);
                int pc = (spc + __popc(p) + h) & 3;   // (-i)^popcount
                float g = (pc & 2) ? -f : f;
                rr[h] = (pc & 1) ? 0.0f : g;
                ii[h] = (pc & 1) ? -g : 0.0f;
            }
            R[p] = pk(rr[0], rr[1]);
            I[p] = pk(ii[0], ii[1]);
        }

        // ---- 3 layers ----
        for (int l = 0; l < 3; l++) {
            const int base = l * 9;
            // phase A gates: qubits 0..4 (bits 8..4)
            gate16<3>(R, I, s_m00[base + 0], s_m01[base + 0]);   // q0: p bit3
            gate16<2>(R, I, s_m00[base + 1], s_m01[base + 1]);   // q1
            gate16<1>(R, I, s_m00[base + 2], s_m01[base + 2]);   // q2
            gate16<0>(R, I, s_m00[base + 3], s_m01[base + 3]);   // q3
            gate16_in (R, I, s_m00[base + 4], s_m01[base + 4]);  // q4: in-pack

            // ---- transpose A -> B (pure layout swap through shared) ----
            __syncwarp();
#pragma unroll
            for (int p = 0; p < 16; p++) {
                float r0, r1, i0, i1;
                up(R[p], r0, r1); up(I[p], i0, i1);
                int a0 = ((p >> 3) << 8) | (sl << 4) | ((p & 7) << 1);  // h=0
                buf[a0 ^ sl]       = make_float2(r0, i0);
                buf[(a0 | 1) ^ sl] = make_float2(r1, i1);
            }
            __syncwarp();
#pragma unroll
            for (int p = 0; p < 16; p++) {       // p plays p' here
                int k0 = p << 1;                 // h'=0
                float2 v0 = buf[((k0 << 4) | sl) ^ (k0 & 15)];
                int k1 = k0 | 1;                 // h'=1
                float2 v1 = buf[((k1 << 4) | sl) ^ (k1 & 15)];
                R[p] = pk(v0.x, v1.x);
                I[p] = pk(v0.y, v1.y);
            }

            // phase B gates: qubits 5..8 (bits 3..0)
            gate16<2>(R, I, s_m00[base + 5], s_m01[base + 5]);   // q5: p' bit2
            gate16<1>(R, I, s_m00[base + 6], s_m01[base + 6]);   // q6
            gate16<0>(R, I, s_m00[base + 7], s_m01[base + 7]);   // q7
            gate16_in (R, I, s_m00[base + 8], s_m01[base + 8]);  // q8: in-pack

            // ---- B -> A, composing the CNOT-ring permutation ----
            const unsigned short* pm = s_perm + (l << 9);
            __syncwarp();
#pragma unroll
            for (int p = 0; p < 16; p++) {
                int k0 = p << 1;
                int i0 = ((k0 >> 4) << 8) | (sl << 4) | (k0 & 15);  // basis index, h'=0
                float r0, r1, i0f, i1f;
                up(R[p], r0, r1); up(I[p], i0f, i1f);
                buf[pm[i0]]     = make_float2(r0, i0f);
                buf[pm[i0 | 1]] = make_float2(r1, i1f);
            }
            __syncwarp();
#pragma unroll
            for (int p = 0; p < 16; p++) {
                int iA0 = (p << 5) | sl;         // h=0
                int iA1 = iA0 | 16;              // h=1
                float2 v0 = buf[iA0 ^ ((iA0 >> 4) & 15)];
                float2 v1 = buf[iA1 ^ ((iA1 >> 4) & 15)];
                R[p] = pk(v0.x, v1.x);
                I[p] = pk(v0.y, v1.y);
            }
        }

        // ---- measurement: <Z_w>, state in phase A layout ----
        float pr0[16], pr1[16];
#pragma unroll
        for (int p = 0; p < 16; p++) {
            u64 P2 = f2fma(R[p], R[p], f2mul(I[p], I[p]));
            up(P2, pr0[p], pr1[p]);
        }
        float acc[9];
#pragma unroll
        for (int w = 0; w < 4; w++) {            // qubits 0..3: sign from p bits
            float s = 0.0f;
#pragma unroll
            for (int p = 0; p < 16; p++) {
                float t = pr0[p] + pr1[p];
                s += ((p >> (3 - w)) & 1) ? -t : t;
            }
            acc[w] = s;
        }
        {                                        // qubit 4: sign from in-pack half
            float s = 0.0f;
#pragma unroll
            for (int p = 0; p < 16; p++) s += pr0[p] - pr1[p];
            acc[4] = s;
        }
        float T = 0.0f;
#pragma unroll
        for (int p = 0; p < 16; p++) T += pr0[p] + pr1[p];
#pragma unroll
        for (int w = 5; w < 9; w++)              // qubits 5..8: sign from sl bits
            acc[w] = ((sl >> (8 - w)) & 1) ? -T : T;

        // half-warp reduction (xor offsets stay inside the half)
#pragma unroll
        for (int off = 8; off > 0; off >>= 1) {
#pragma unroll
            for (int w = 0; w < 9; w++)
                acc[w] += __shfl_xor_sync(FULL_MASK, acc[w], off);
        }
        if (sl == 0) {
#pragma unroll
            for (int w = 0; w < 9; w++) out[b * 9 + w] = acc[w];
        }
    }
}

extern "C" void kernel_launch(void* const* d_in, const int* in_sizes, int n_in,
                              void* d_out, int out_size) {
    const float* x  = (const float*)d_in[0];   // (32768, 9) fp32
    const float* wt = (const float*)d_in[1];   // (3, 9, 3) fp32
    float* out = (float*)d_out;                // (32768, 9) fp32
    int B = in_sizes[0] / 9;
    qsim_kernel<<<2048, 128>>>(x, wt, out, B);
}

// round 8
// speedup vs baseline: 1.4785x; 1.4785x over previous
#include <cuda_runtime.h>

#define FULL_MASK 0xffffffffu
typedef unsigned long long u64;

// ---- f32x2 packed helpers (sm_103a FFMA2/FADD2 only reachable via PTX) ----
__device__ __forceinline__ u64 pk(float lo, float hi) {
    u64 r; asm("mov.b64 %0,{%1,%2};" : "=l"(r) : "f"(lo), "f"(hi)); return r;
}
__device__ __forceinline__ void up(u64 v, float& lo, float& hi) {
    asm("mov.b64 {%0,%1},%2;" : "=f"(lo), "=f"(hi) : "l"(v));
}
__device__ __forceinline__ u64 f2fma(u64 a, u64 b, u64 c) {
    u64 d; asm("fma.rn.f32x2 %0,%1,%2,%3;" : "=l"(d) : "l"(a), "l"(b), "l"(c)); return d;
}
__device__ __forceinline__ u64 f2mul(u64 a, u64 b) {
    u64 d; asm("mul.rn.f32x2 %0,%1,%2;" : "=l"(d) : "l"(a), "l"(b)); return d;
}
__device__ __forceinline__ u64 f2add(u64 a, u64 b) {
    u64 d; asm("add.rn.f32x2 %0,%1,%2;" : "=l"(d) : "l"(a), "l"(b)); return d;
}
__device__ __forceinline__ u64 swp(u64 v) {
    float a, b; up(v, a, b); return pk(b, a);
}

// packed complex multiply by broadcast scalar (yr,yi): dst = src * y
__device__ __forceinline__ void cmulp(u64& Rd, u64& Id, u64 Rs, u64 Is,
                                      float yr, float yi) {
    u64 pyr = pk(yr, yr), pyi = pk(yi, yi), nyi = pk(-yi, -yi);
    Rd = f2fma(Rs, pyr, f2mul(Is, nyi));
    Id = f2fma(Rs, pyi, f2mul(Is, pyr));
}

// ---- compile-time CNOT-ring permutations (data-independent!) ----
__host__ __device__ constexpr int perm_apply(int r, int v) {
    for (int g = 0; g < 9; g++) {
        int t = g + r; if (t >= 9) t -= 9;
        v ^= ((v >> (8 - g)) & 1) << (8 - t);
    }
    return v;
}
// mask of input bits whose parity gives output bit t of perm layer 2 (r=3)
__host__ __device__ constexpr int mask_bit(int t) {
    int m = 0;
    for (int b = 0; b < 9; b++)
        if ((perm_apply(3, 1 << b) >> t) & 1) m |= (1 << b);
    return m;
}

// ============================================================================
// Layout: amp index i = k*32 + lane.
//   lane bits 0..4 -> qubits 8..4 ; k bits 0..3 -> qubits 3..0
// Packs: R[p]/I[p] hold k=2p (lo half) and k=2p+1 (hi half).
// ============================================================================
__device__ __forceinline__ int swz(int i) { return i ^ ((i >> 5) & 15); }

// Gate on k-bit (PB+1), PB in {0,1,2}.  m10=-conj(m01), m11=conj(m00).
template <int PB>
__device__ __forceinline__ void gate_reg(u64 (&R)[8], u64 (&I)[8],
                                         float2 m00, float2 m01) {
    const u64 c00x = pk(m00.x, m00.x), c00y = pk(m00.y, m00.y);
    const u64 c01x = pk(m01.x, m01.x), c01y = pk(m01.y, m01.y);
    const u64 n00y = pk(-m00.y, -m00.y), n01x = pk(-m01.x, -m01.x);
    const u64 n01y = pk(-m01.y, -m01.y);
    const int d = 1 << PB;
#pragma unroll
    for (int t = 0; t < 4; t++) {
        const int q = ((t >> PB) << (PB + 1)) | (t & (d - 1));
        const int j = q | d;
        u64 A = R[q], Ai = I[q], Bv = R[j], Bi = I[j];
        R[q] = f2fma(c00x, A,  f2fma(n00y, Ai, f2fma(c01x, Bv, f2mul(n01y, Bi))));
        I[q] = f2fma(c00x, Ai, f2fma(c00y, A,  f2fma(c01x, Bi, f2mul(c01y, Bv))));
        R[j] = f2fma(n01x, A,  f2fma(n01y, Ai, f2fma(c00x, Bv, f2mul(c00y, Bi))));
        I[j] = f2fma(n01x, Ai, f2fma(c01y, A,  f2fma(c00x, Bi, f2mul(n00y, Bv))));
    }
}

// Gate on k-bit 0 (in-pack butterfly).
__device__ __forceinline__ void gate_reg0(u64 (&R)[8], u64 (&I)[8],
                                          float2 m00, float2 m01) {
    const u64 c00x = pk(m00.x, m00.x);
    const u64 cA = pk(-m00.y,  m00.y);
    const u64 cB = pk( m00.y, -m00.y);
    const u64 cC = pk( m01.x, -m01.x);
    const u64 cD = pk(-m01.y, -m01.y);
    const u64 cE = pk( m01.y,  m01.y);
#pragma unroll
    for (int p = 0; p < 8; p++) {
        u64 sR = swp(R[p]), sI = swp(I[p]);
        u64 Rn = f2fma(c00x, R[p], f2fma(cA, I[p], f2fma(cC, sR, f2mul(cD, sI))));
        u64 In = f2fma(c00x, I[p], f2fma(cB, R[p], f2fma(cC, sI, f2mul(cE, sR))));
        R[p] = Rn; I[p] = In;
    }
}

// Gate on lane bit P (qubit 8-P): shfl butterfly.
template <int P>
__device__ __forceinline__ void gate_cross(u64 (&R)[8], u64 (&I)[8],
                                           float2 m00, float2 m01, int lane) {
    const int msk = 1 << P;
    const bool hi = (lane & msk) != 0;
    const float cmr = m00.x;
    const float cmi = hi ? -m00.y : m00.y;
    const float cpr = hi ? -m01.x : m01.x;
    const float cpi = m01.y;
    const u64 kmr = pk(cmr, cmr), kmi = pk(cmi, cmi), nmi = pk(-cmi, -cmi);
    const u64 kpr = pk(cpr, cpr), kpi = pk(cpi, cpi), npi = pk(-cpi, -cpi);
#pragma unroll
    for (int p = 0; p < 8; p++) {
        u64 shR = __shfl_xor_sync(FULL_MASK, R[p], msk);
        u64 shI = __shfl_xor_sync(FULL_MASK, I[p], msk);
        u64 Rn = f2fma(kmr, R[p], f2fma(nmi, I[p], f2fma(kpr, shR, f2mul(npi, shI))));
        u64 In = f2fma(kmr, I[p], f2fma(kmi, R[p], f2fma(kpr, shI, f2mul(kpi, shR))));
        R[p] = Rn; I[p] = In;
    }
}

__global__ void __launch_bounds__(256)
qsim_kernel(const float* __restrict__ x, const float* __restrict__ wt,
            float* __restrict__ out, int B) {
    __shared__ float2 s_m00[27];
    __shared__ float2 s_m01[27];
    __shared__ ushort2 s_perm[2 * 256];          // layers 0,1; pre-swizzled pairs
    __shared__ float2 s_buf[8][512];

    const int tid = threadIdx.x;

    // ---- 27 rotation matrices (m00, m01; m10/m11 derived) ----
    if (tid < 27) {
        const float* p = wt + tid * 3;
        float phi = p[0], th = p[1], om = p[2];
        float a  = 0.5f * (phi + om);
        float bb = 0.5f * (phi - om);
        float c = cosf(0.5f * th), s = sinf(0.5f * th);
        float ca = cosf(a),  sa = sinf(a);
        float cb = cosf(bb), sb = sinf(bb);
        s_m00[tid] = make_float2(c * ca, -c * sa);   // e^{-i a} c
        s_m01[tid] = make_float2(-s * cb, -s * sb);  // -e^{i b} s
    }
    // ---- perm tables for layers 0,1 (scatter dests, swizzle folded) ----
    for (int e = tid; e < 2 * 256; e += blockDim.x) {
        int l = e >> 8, idx = e & 255;
        int p = idx >> 5, ln = idx & 31;
        int i0 = p * 64 + ln;                     // k = 2p
        int i1 = i0 + 32;                         // k = 2p+1
        int r = l + 1;
        int v0 = i0, v1 = i1;
#pragma unroll
        for (int g = 0; g < 9; g++) {
            int t = g + r; if (t >= 9) t -= 9;
            v0 ^= ((v0 >> (8 - g)) & 1) << (8 - t);
            v1 ^= ((v1 >> (8 - g)) & 1) << (8 - t);
        }
        s_perm[e] = make_ushort2((unsigned short)swz(v0), (unsigned short)swz(v1));
    }
    __syncthreads();

    const int lane = tid & 31;
    const int warp = tid >> 5;
    float2* buf = s_buf[warp];
    const int gw = blockIdx.x * (blockDim.x >> 5) + warp;
    const int nw = gridDim.x * (blockDim.x >> 5);

    for (int b = gw; b < B; b += nw) {
        // ---- per-qubit angles ----
        float cs[9], sn[9];
#pragma unroll
        for (int w = 0; w < 9; w++) {
            float h2 = 0.5f * __ldg(&x[b * 9 + w]);
            __sincosf(h2, &sn[w], &cs[w]);
        }

        // ---- layer-0 rotations folded into per-qubit 2-vectors ----
        // qubit w rotated state: a_w (bit=0), b_w (bit=1):
        //   a = (m00r c + m01i s,  m00i c - m01r s)
        //   b = (-m01r c - m00i s, m01i c - m00r s)
        // lane factor: product over lane bits p=0..4 of qubit 8-p's a or b
        float Lr = 1.0f, Li = 0.0f;
#pragma unroll
        for (int p = 0; p < 5; p++) {
            int w = 8 - p;
            float2 m0 = s_m00[w], m1 = s_m01[w];
            float c = cs[w], s = sn[w];
            float vr, vi;
            if ((lane >> p) & 1) { vr = -m1.x * c - m0.y * s; vi = m1.y * c - m0.x * s; }
            else                 { vr =  m0.x * c + m1.y * s; vi = m0.y * c - m1.x * s; }
            float nr = Lr * vr - Li * vi;
            Li = Lr * vi + Li * vr;
            Lr = nr;
        }
        float awr[4], awi[4], bwr[4], bwi[4];
#pragma unroll
        for (int w = 0; w < 4; w++) {
            float2 m0 = s_m00[w], m1 = s_m01[w];
            float c = cs[w], s = sn[w];
            awr[w] =  m0.x * c + m1.y * s;  awi[w] = m0.y * c - m1.x * s;
            bwr[w] = -m1.x * c - m0.y * s;  bwi[w] = m1.y * c - m0.x * s;
        }
        // fold lane factor into qubit-0 factors (last doubling step)
        float A0r = awr[0] * Lr - awi[0] * Li, A0i = awr[0] * Li + awi[0] * Lr;
        float B0r = bwr[0] * Lr - bwi[0] * Li, B0i = bwr[0] * Li + bwi[0] * Lr;

        // ---- build state by packed doubling over k bits ----
        u64 R[8], I[8];
        R[0] = pk(awr[3], bwr[3]); I[0] = pk(awi[3], bwi[3]);      // k bit0 = qubit 3
        cmulp(R[1], I[1], R[0], I[0], bwr[2], bwi[2]);             // k bit1 = qubit 2
        cmulp(R[0], I[0], R[0], I[0], awr[2], awi[2]);
        cmulp(R[2], I[2], R[0], I[0], bwr[1], bwi[1]);             // k bit2 = qubit 1
        cmulp(R[3], I[3], R[1], I[1], bwr[1], bwi[1]);
        cmulp(R[0], I[0], R[0], I[0], awr[1], awi[1]);
        cmulp(R[1], I[1], R[1], I[1], awr[1], awi[1]);
#pragma unroll
        for (int p = 0; p < 4; p++)                                // k bit3 = qubit 0 (+L)
            cmulp(R[p + 4], I[p + 4], R[p], I[p], B0r, B0i);
#pragma unroll
        for (int p = 0; p < 4; p++)
            cmulp(R[p], I[p], R[p], I[p], A0r, A0i);

        // ---- C0 perm, layer-1 gates, C1 perm, layer-2 gates ----
#pragma unroll
        for (int l = 0; l < 2; l++) {
            // CNOT-ring permutation l (scatter through shared)
            const ushort2* pm = s_perm + (l << 8);
            __syncwarp();
#pragma unroll
            for (int p = 0; p < 8; p++) {
                float r0, r1, i0f, i1f;
                up(R[p], r0, r1); up(I[p], i0f, i1f);
                ushort2 d = pm[p * 32 + lane];
                buf[d.x] = make_float2(r0, i0f);
                buf[d.y] = make_float2(r1, i1f);
            }
            __syncwarp();
#pragma unroll
            for (int p = 0; p < 8; p++) {
                int i0 = p * 64 + lane, i1 = i0 + 32;
                float2 v0 = buf[swz(i0)];
                float2 v1 = buf[swz(i1)];
                R[p] = pk(v0.x, v1.x);
                I[p] = pk(v0.y, v1.y);
            }
            // rotation layer l+1
            const int base = (l + 1) * 9;
            gate_reg<2>(R, I, s_m00[base + 0], s_m01[base + 0]);   // qubit 0
            gate_reg<1>(R, I, s_m00[base + 1], s_m01[base + 1]);   // qubit 1
            gate_reg<0>(R, I, s_m00[base + 2], s_m01[base + 2]);   // qubit 2
            gate_reg0  (R, I, s_m00[base + 3], s_m01[base + 3]);   // qubit 3
            gate_cross<4>(R, I, s_m00[base + 4], s_m01[base + 4], lane);
            gate_cross<3>(R, I, s_m00[base + 5], s_m01[base + 5], lane);
            gate_cross<2>(R, I, s_m00[base + 6], s_m01[base + 6], lane);
            gate_cross<1>(R, I, s_m00[base + 7], s_m01[base + 7], lane);
            gate_cross<0>(R, I, s_m00[base + 8], s_m01[base + 8], lane);
        }

        // ---- measurement with final CNOT layer folded in as parity masks ----
        u64 P[8];
        const u64 NEG1 = pk(-1.0f, -1.0f);
#pragma unroll
        for (int p = 0; p < 8; p++)
            P[p] = f2fma(R[p], R[p], f2mul(I[p], I[p]));
        // packed Walsh-Hadamard over pack bits (k bits 1..3)
#pragma unroll
        for (int j = 0; j < 3; j++) {
            const int d = 1 << j;
#pragma unroll
            for (int t = 0; t < 4; t++) {
                const int q = ((t >> j) << (j + 1)) | (t & (d - 1));
                const int v = q | d;
                u64 a = P[q], bb = P[v];
                P[q] = f2add(a, bb);
                P[v] = f2fma(bb, NEG1, a);
            }
        }
        // final stage over k bit 0 (in-pack)
        float S[16];
#pragma unroll
        for (int p = 0; p < 8; p++) {
            float lo, hi; up(P[p], lo, hi);
            S[2 * p]     = lo + hi;
            S[2 * p + 1] = lo - hi;
        }
        // <Z_w> = ±S[kmask], masks from compile-time perm layer 2
        constexpr int MT[9] = { mask_bit(0), mask_bit(1), mask_bit(2),
                                mask_bit(3), mask_bit(4), mask_bit(5),
                                mask_bit(6), mask_bit(7), mask_bit(8) };
        float acc[9];
#pragma unroll
        for (int w = 0; w < 9; w++) {
            const int mk = MT[8 - w];
            float v = S[mk >> 5];
            acc[w] = (__popc(mk & 31 & lane) & 1) ? -v : v;
        }
#pragma unroll
        for (int off = 16; off > 0; off >>= 1) {
#pragma unroll
            for (int w = 0; w < 9; w++)
                acc[w] += __shfl_xor_sync(FULL_MASK, acc[w], off);
        }
        if (lane == 0) {
#pragma unroll
            for (int w = 0; w < 9; w++) out[b * 9 + w] = acc[w];
        }
    }
}

extern "C" void kernel_launch(void* const* d_in, const int* in_sizes, int n_in,
                              void* d_out, int out_size) {
    const float* x  = (const float*)d_in[0];   // (32768, 9) fp32
    const float* wt = (const float*)d_in[1];   // (3, 9, 3) fp32
    float* out = (float*)d_out;                // (32768, 9) fp32
    int B = in_sizes[0] / 9;
    qsim_kernel<<<2048, 256>>>(x, wt, out, B);
}

// round 9
// speedup vs baseline: 1.9356x; 1.3091x over previous
#include <cuda_runtime.h>

#define FULL_MASK 0xffffffffu
typedef unsigned long long u64;

// ---- f32x2 packed helpers (sm_103a FFMA2/FADD2 only reachable via PTX) ----
__device__ __forceinline__ u64 pk(float lo, float hi) {
    u64 r; asm("mov.b64 %0,{%1,%2};" : "=l"(r) : "f"(lo), "f"(hi)); return r;
}
__device__ __forceinline__ void up(u64 v, float& lo, float& hi) {
    asm("mov.b64 {%0,%1},%2;" : "=f"(lo), "=f"(hi) : "l"(v));
}
__device__ __forceinline__ u64 f2fma(u64 a, u64 b, u64 c) {
    u64 d; asm("fma.rn.f32x2 %0,%1,%2,%3;" : "=l"(d) : "l"(a), "l"(b), "l"(c)); return d;
}
__device__ __forceinline__ u64 f2mul(u64 a, u64 b) {
    u64 d; asm("mul.rn.f32x2 %0,%1,%2;" : "=l"(d) : "l"(a), "l"(b)); return d;
}
__device__ __forceinline__ u64 f2add(u64 a, u64 b) {
    u64 d; asm("add.rn.f32x2 %0,%1,%2;" : "=l"(d) : "l"(a), "l"(b)); return d;
}
__device__ __forceinline__ u64 swp(u64 v) {
    float a, b; up(v, a, b); return pk(b, a);
}
__device__ __forceinline__ u64 f2neg(u64 v) { return v ^ 0x8000000080000000ULL; }

// packed complex multiply by broadcast scalar (yr,yi): dst = src * y
__device__ __forceinline__ void cmulp(u64& Rd, u64& Id, u64 Rs, u64 Is,
                                      float yr, float yi) {
    u64 pyr = pk(yr, yr), pyi = pk(yi, yi), nyi = pk(-yi, -yi);
    Rd = f2fma(Rs, pyr, f2mul(Is, nyi));
    Id = f2fma(Rs, pyi, f2mul(Is, pyr));
}

// ---- compile-time CNOT-ring permutations (data-independent) ----
__host__ __device__ constexpr int perm_apply(int r, int v) {
    for (int g = 0; g < 9; g++) {
        int t = g + r; if (t >= 9) t -= 9;
        v ^= ((v >> (8 - g)) & 1) << (8 - t);
    }
    return v;
}
// mask of input bits whose parity gives output bit t of perm layer 2 (r=3)
__host__ __device__ constexpr int mask_bit(int t) {
    int m = 0;
    for (int b = 0; b < 9; b++)
        if ((perm_apply(3, 1 << b) >> t) & 1) m |= (1 << b);
    return m;
}

// ============================================================================
// Layout: amp index i = k*32 + lane.
//   lane bits 0..4 -> qubits 8..4 ; k bits 0..3 -> qubits 3..0
// Packs: R[p]/I[p] hold k=2p (lo half) and k=2p+1 (hi half).
// ============================================================================
__device__ __forceinline__ int swz(int i) { return i ^ ((i >> 5) & 15); }

// ---- RY gates (real coefficients: a' = c a - s b ; b' = s a + c b) ----
template <int PB>
__device__ __forceinline__ void ry_reg(u64 (&R)[8], u64 (&I)[8], float c, float s) {
    const u64 pc = pk(c, c), ps = pk(s, s), ns = pk(-s, -s);
    const int d = 1 << PB;
#pragma unroll
    for (int t = 0; t < 4; t++) {
        const int q = ((t >> PB) << (PB + 1)) | (t & (d - 1));
        const int j = q | d;
        u64 Rq = R[q], Iq = I[q], Rj = R[j], Ij = I[j];
        R[q] = f2fma(pc, Rq, f2mul(ns, Rj));
        I[q] = f2fma(pc, Iq, f2mul(ns, Ij));
        R[j] = f2fma(ps, Rq, f2mul(pc, Rj));
        I[j] = f2fma(ps, Iq, f2mul(pc, Ij));
    }
}
__device__ __forceinline__ void ry_in(u64 (&R)[8], u64 (&I)[8], float c, float s) {
    const u64 pc = pk(c, c), cs2 = pk(-s, s);
#pragma unroll
    for (int p = 0; p < 8; p++) {
        R[p] = f2fma(pc, R[p], f2mul(cs2, swp(R[p])));
        I[p] = f2fma(pc, I[p], f2mul(cs2, swp(I[p])));
    }
}
template <int P>
__device__ __forceinline__ void ry_cross(u64 (&R)[8], u64 (&I)[8],
                                         float c, float s, int lane) {
    const int msk = 1 << P;
    const float sp = (lane & msk) ? s : -s;
    const u64 pc = pk(c, c), psl = pk(sp, sp);
#pragma unroll
    for (int p = 0; p < 8; p++) {
        u64 shR = __shfl_xor_sync(FULL_MASK, R[p], msk);
        u64 shI = __shfl_xor_sync(FULL_MASK, I[p], msk);
        R[p] = f2fma(pc, R[p], f2mul(psl, shR));
        I[p] = f2fma(pc, I[p], f2mul(psl, shI));
    }
}

// ---- precomputed 512-entry diagonal (pack-major packed tables) ----
__device__ __forceinline__ void apply_diag(u64 (&R)[8], u64 (&I)[8],
                                           const float* Tr, const float* Ti,
                                           int lane) {
    const u64* cr = (const u64*)Tr;
    const u64* ci = (const u64*)Ti;
#pragma unroll
    for (int p = 0; p < 8; p++) {
        u64 Cr = cr[p * 32 + lane], Ci = ci[p * 32 + lane];
        u64 Rn = f2fma(R[p], Cr, f2mul(f2neg(I[p]), Ci));
        I[p]   = f2fma(R[p], Ci, f2mul(I[p], Cr));
        R[p] = Rn;
    }
}

__global__ void __launch_bounds__(256)
qsim_kernel(const float* __restrict__ x, const float* __restrict__ wt,
            float* __restrict__ out, int B) {
    __shared__ float2 s_m00[9], s_m01[9];        // layer-0 Rot (for init fold)
    __shared__ float2 s_ry[18];                  // (c, s) layers 1,2
    __shared__ float2 s_ph[3][9];                // e^{-i ang/2}: [0]=phi1 [1]=omega1 [2]=phi2
    __shared__ ushort2 s_perm[2 * 256];          // C0, C1 scatter dests (swizzled)
    __shared__ float s_T1r[512], s_T1i[512];     // D1(layer1) pack-major
    __shared__ float s_TEr[512], s_TEi[512];     // D2(layer1)*C1-conj(D1(layer2))
    __shared__ float2 s_buf[8][512];

    const int tid = threadIdx.x;

    // ---- per-layer gate data ----
    if (tid < 27) {
        const int l = tid / 9, w = tid % 9;
        const float* p = wt + tid * 3;
        float phi = p[0], th = p[1], om = p[2];
        float c, s;
        __sincosf(0.5f * th, &s, &c);
        if (l == 0) {
            float a  = 0.5f * (phi + om);
            float bb = 0.5f * (phi - om);
            float ca, sa, cb, sb;
            __sincosf(a, &sa, &ca);
            __sincosf(bb, &sb, &cb);
            s_m00[w] = make_float2(c * ca, -c * sa);
            s_m01[w] = make_float2(-s * cb, -s * sb);
        } else {
            s_ry[(l - 1) * 9 + w] = make_float2(c, s);
            float cp, sp;
            __sincosf(0.5f * phi, &sp, &cp);
            if (l == 1) {
                s_ph[0][w] = make_float2(cp, -sp);
                float co, so;
                __sincosf(0.5f * om, &so, &co);
                s_ph[1][w] = make_float2(co, -so);
            } else {
                s_ph[2][w] = make_float2(cp, -sp);
            }
        }
    }
    // ---- perm scatter tables for C0, C1 ----
    for (int e = tid; e < 2 * 256; e += blockDim.x) {
        int l = e >> 8, idx = e & 255;
        int p = idx >> 5, ln = idx & 31;
        int i0 = p * 64 + ln, i1 = i0 + 32;
        int v0 = perm_apply(l + 1, i0);
        int v1 = perm_apply(l + 1, i1);
        s_perm[e] = make_ushort2((unsigned short)swz(v0), (unsigned short)swz(v1));
    }
    __syncthreads();

    // ---- build diagonal tables (weights-only; once per block) ----
    for (int i = tid; i < 512; i += blockDim.x) {
        float t1r = 1.0f, t1i = 0.0f, ter = 1.0f, tei = 0.0f;
        int ci = perm_apply(2, i);
#pragma unroll
        for (int w = 0; w < 9; w++) {
            int b0 = (i >> (8 - w)) & 1;
            int b1 = (ci >> (8 - w)) & 1;
            float2 p0 = s_ph[0][w];
            float y0 = b0 ? -p0.y : p0.y;
            float nr = t1r * p0.x - t1i * y0;
            t1i = t1r * y0 + t1i * p0.x; t1r = nr;
            float2 p1 = s_ph[1][w];
            float y1 = b0 ? -p1.y : p1.y;
            nr = ter * p1.x - tei * y1;
            tei = ter * y1 + tei * p1.x; ter = nr;
            float2 p2 = s_ph[2][w];
            float y2 = b1 ? -p2.y : p2.y;
            nr = ter * p2.x - tei * y2;
            tei = ter * y2 + tei * p2.x; ter = nr;
        }
        int k = i >> 5, ln = i & 31;
        int fi = ((k >> 1) * 32 + ln) * 2 + (k & 1);
        s_T1r[fi] = t1r; s_T1i[fi] = t1i;
        s_TEr[fi] = ter; s_TEi[fi] = tei;
    }
    __syncthreads();

    const int lane = tid & 31;
    const int warp = tid >> 5;
    float2* buf = s_buf[warp];
    const int gw = blockIdx.x * (blockDim.x >> 5) + warp;
    const int nw = gridDim.x * (blockDim.x >> 5);

    for (int b = gw; b < B; b += nw) {
        // ---- per-qubit angles ----
        float cs[9], sn[9];
#pragma unroll
        for (int w = 0; w < 9; w++) {
            float h2 = 0.5f * __ldg(&x[b * 9 + w]);
            __sincosf(h2, &sn[w], &cs[w]);
        }

        // ---- layer-0 rotations folded into per-qubit 2-vectors ----
        float Lr = 1.0f, Li = 0.0f;
#pragma unroll
        for (int p = 0; p < 5; p++) {
            int w = 8 - p;
            float2 m0 = s_m00[w], m1 = s_m01[w];
            float c = cs[w], s = sn[w];
            float vr, vi;
            if ((lane >> p) & 1) { vr = -m1.x * c - m0.y * s; vi = m1.y * c - m0.x * s; }
            else                 { vr =  m0.x * c + m1.y * s; vi = m0.y * c - m1.x * s; }
            float nr = Lr * vr - Li * vi;
            Li = Lr * vi + Li * vr;
            Lr = nr;
        }
        float awr[4], awi[4], bwr[4], bwi[4];
#pragma unroll
        for (int w = 0; w < 4; w++) {
            float2 m0 = s_m00[w], m1 = s_m01[w];
            float c = cs[w], s = sn[w];
            awr[w] =  m0.x * c + m1.y * s;  awi[w] = m0.y * c - m1.x * s;
            bwr[w] = -m1.x * c - m0.y * s;  bwi[w] = m1.y * c - m0.x * s;
        }
        float A0r = awr[0] * Lr - awi[0] * Li, A0i = awr[0] * Li + awi[0] * Lr;
        float B0r = bwr[0] * Lr - bwi[0] * Li, B0i = bwr[0] * Li + bwi[0] * Lr;

        // ---- build state by packed doubling over k bits ----
        u64 R[8], I[8];
        R[0] = pk(awr[3], bwr[3]); I[0] = pk(awi[3], bwi[3]);
        cmulp(R[1], I[1], R[0], I[0], bwr[2], bwi[2]);
        cmulp(R[0], I[0], R[0], I[0], awr[2], awi[2]);
        cmulp(R[2], I[2], R[0], I[0], bwr[1], bwi[1]);
        cmulp(R[3], I[3], R[1], I[1], bwr[1], bwi[1]);
        cmulp(R[0], I[0], R[0], I[0], awr[1], awi[1]);
        cmulp(R[1], I[1], R[1], I[1], awr[1], awi[1]);
#pragma unroll
        for (int p = 0; p < 4; p++)
            cmulp(R[p + 4], I[p + 4], R[p], I[p], B0r, B0i);
#pragma unroll
        for (int p = 0; p < 4; p++)
            cmulp(R[p], I[p], R[p], I[p], A0r, A0i);

        // ---- C0 permutation ----
        {
            const ushort2* pm = s_perm;
            __syncwarp();
#pragma unroll
            for (int p = 0; p < 8; p++) {
                float r0, r1, i0f, i1f;
                up(R[p], r0, r1); up(I[p], i0f, i1f);
                ushort2 d = pm[p * 32 + lane];
                buf[d.x] = make_float2(r0, i0f);
                buf[d.y] = make_float2(r1, i1f);
            }
            __syncwarp();
#pragma unroll
            for (int p = 0; p < 8; p++) {
                float2 v0 = buf[swz(p * 64 + lane)];
                float2 v1 = buf[swz(p * 64 + 32 + lane)];
                R[p] = pk(v0.x, v1.x);
                I[p] = pk(v0.y, v1.y);
            }
        }

        // ---- D1(layer1) diag ----
        apply_diag(R, I, s_T1r, s_T1i, lane);

        // ---- RY sweep, layer 1 ----
        ry_reg<2>(R, I, s_ry[0].x, s_ry[0].y);           // qubit 0 (k bit 3)
        ry_reg<1>(R, I, s_ry[1].x, s_ry[1].y);           // qubit 1
        ry_reg<0>(R, I, s_ry[2].x, s_ry[2].y);           // qubit 2
        ry_in    (R, I, s_ry[3].x, s_ry[3].y);           // qubit 3 (in-pack)
        ry_cross<4>(R, I, s_ry[4].x, s_ry[4].y, lane);   // qubit 4
        ry_cross<3>(R, I, s_ry[5].x, s_ry[5].y, lane);
        ry_cross<2>(R, I, s_ry[6].x, s_ry[6].y, lane);
        ry_cross<1>(R, I, s_ry[7].x, s_ry[7].y, lane);
        ry_cross<0>(R, I, s_ry[8].x, s_ry[8].y, lane);   // qubit 8

        // ---- E = D2(layer1) * C1-conjugated D1(layer2) ----
        apply_diag(R, I, s_TEr, s_TEi, lane);

        // ---- C1 permutation ----
        {
            const ushort2* pm = s_perm + 256;
            __syncwarp();
#pragma unroll
            for (int p = 0; p < 8; p++) {
                float r0, r1, i0f, i1f;
                up(R[p], r0, r1); up(I[p], i0f, i1f);
                ushort2 d = pm[p * 32 + lane];
                buf[d.x] = make_float2(r0, i0f);
                buf[d.y] = make_float2(r1, i1f);
            }
            __syncwarp();
#pragma unroll
            for (int p = 0; p < 8; p++) {
                float2 v0 = buf[swz(p * 64 + lane)];
                float2 v1 = buf[swz(p * 64 + 32 + lane)];
                R[p] = pk(v0.x, v1.x);
                I[p] = pk(v0.y, v1.y);
            }
        }

        // ---- RY sweep, layer 2  (D2(layer2) dropped: pure phase) ----
        ry_reg<2>(R, I, s_ry[9].x,  s_ry[9].y);
        ry_reg<1>(R, I, s_ry[10].x, s_ry[10].y);
        ry_reg<0>(R, I, s_ry[11].x, s_ry[11].y);
        ry_in    (R, I, s_ry[12].x, s_ry[12].y);
        ry_cross<4>(R, I, s_ry[13].x, s_ry[13].y, lane);
        ry_cross<3>(R, I, s_ry[14].x, s_ry[14].y, lane);
        ry_cross<2>(R, I, s_ry[15].x, s_ry[15].y, lane);
        ry_cross<1>(R, I, s_ry[16].x, s_ry[16].y, lane);
        ry_cross<0>(R, I, s_ry[17].x, s_ry[17].y, lane);

        // ---- measurement with final CNOT layer folded in as parity masks ----
        u64 P[8];
        const u64 NEG1 = pk(-1.0f, -1.0f);
#pragma unroll
        for (int p = 0; p < 8; p++)
            P[p] = f2fma(R[p], R[p], f2mul(I[p], I[p]));
#pragma unroll
        for (int j = 0; j < 3; j++) {
            const int d = 1 << j;
#pragma unroll
            for (int t = 0; t < 4; t++) {
                const int q = ((t >> j) << (j + 1)) | (t & (d - 1));
                const int v = q | d;
                u64 a = P[q], bb = P[v];
                P[q] = f2add(a, bb);
                P[v] = f2fma(bb, NEG1, a);
            }
        }
        float S[16];
#pragma unroll
        for (int p = 0; p < 8; p++) {
            float lo, hi; up(P[p], lo, hi);
            S[2 * p]     = lo + hi;
            S[2 * p + 1] = lo - hi;
        }
        constexpr int MT[9] = { mask_bit(0), mask_bit(1), mask_bit(2),
                                mask_bit(3), mask_bit(4), mask_bit(5),
                                mask_bit(6), mask_bit(7), mask_bit(8) };
        float acc[9];
#pragma unroll
        for (int w = 0; w < 9; w++) {
            const int mk = MT[8 - w];
            float v = S[mk >> 5];
            acc[w] = (__popc(mk & 31 & lane) & 1) ? -v : v;
        }
        // packed warp reduction
        u64 ac[4];
#pragma unroll
        for (int j = 0; j < 4; j++) ac[j] = pk(acc[2 * j], acc[2 * j + 1]);
        float a8 = acc[8];
#pragma unroll
        for (int off = 16; off > 0; off >>= 1) {
#pragma unroll
            for (int j = 0; j < 4; j++)
                ac[j] = f2add(ac[j], __shfl_xor_sync(FULL_MASK, ac[j], off));
            a8 += __shfl_xor_sync(FULL_MASK, a8, off);
        }
        if (lane == 0) {
#pragma unroll
            for (int j = 0; j < 4; j++) {
                float lo, hi; up(ac[j], lo, hi);
                out[b * 9 + 2 * j]     = lo;
                out[b * 9 + 2 * j + 1] = hi;
            }
            out[b * 9 + 8] = a8;
        }
    }
}

extern "C" void kernel_launch(void* const* d_in, const int* in_sizes, int n_in,
                              void* d_out, int out_size) {
    const float* x  = (const float*)d_in[0];   // (32768, 9) fp32
    const float* wt = (const float*)d_in[1];   // (3, 9, 3) fp32
    float* out = (float*)d_out;                // (32768, 9) fp32
    int B = in_sizes[0] / 9;
    qsim_kernel<<<2048, 256>>>(x, wt, out, B);
}

// round 13
// speedup vs baseline: 1.9497x; 1.0073x over previous
#include <cuda_runtime.h>

#define FULL_MASK 0xffffffffu
typedef unsigned long long u64;

// ---- f32x2 packed helpers (sm_103a FFMA2/FADD2 only reachable via PTX) ----
__device__ __forceinline__ u64 pk(float lo, float hi) {
    u64 r; asm("mov.b64 %0,{%1,%2};" : "=l"(r) : "f"(lo), "f"(hi)); return r;
}
__device__ __forceinline__ void up(u64 v, float& lo, float& hi) {
    asm("mov.b64 {%0,%1},%2;" : "=f"(lo), "=f"(hi) : "l"(v));
}
__device__ __forceinline__ u64 f2fma(u64 a, u64 b, u64 c) {
    u64 d; asm("fma.rn.f32x2 %0,%1,%2,%3;" : "=l"(d) : "l"(a), "l"(b), "l"(c)); return d;
}
__device__ __forceinline__ u64 f2mul(u64 a, u64 b) {
    u64 d; asm("mul.rn.f32x2 %0,%1,%2;" : "=l"(d) : "l"(a), "l"(b)); return d;
}
__device__ __forceinline__ u64 f2add(u64 a, u64 b) {
    u64 d; asm("add.rn.f32x2 %0,%1,%2;" : "=l"(d) : "l"(a), "l"(b)); return d;
}
__device__ __forceinline__ u64 swp(u64 v) {
    float a, b; up(v, a, b); return pk(b, a);
}
__device__ __forceinline__ u64 f2neg(u64 v) { return v ^ 0x8000000080000000ULL; }

// packed complex multiply by broadcast scalar (yr,yi): dst = src * y
__device__ __forceinline__ void cmulp(u64& Rd, u64& Id, u64 Rs, u64 Is,
                                      float yr, float yi) {
    u64 pyr = pk(yr, yr), pyi = pk(yi, yi), nyi = pk(-yi, -yi);
    Rd = f2fma(Rs, pyr, f2mul(Is, nyi));
    Id = f2fma(Rs, pyi, f2mul(Is, pyr));
}

// ---- compile-time CNOT-ring permutations & layout maps ----
__host__ __device__ constexpr int perm_apply(int r, int v) {
    for (int g = 0; g < 9; g++) {
        int t = g + r; if (t >= 9) t -= 9;
        v ^= ((v >> (8 - g)) & 1) << (8 - t);
    }
    return v;
}
__host__ __device__ constexpr int mask_bit(int t) {
    int m = 0;
    for (int b = 0; b < 9; b++)
        if ((perm_apply(3, 1 << b) >> t) & 1) m |= (1 << b);
    return m;
}
// Layout A: i = v (lane = v bits 0..4 = qubits 8..4; k = v bits 5..8 = qubits 3..0)
// Layout B: k' = v bits 1..4 (qubits 7..4; k' bit0 in-pack);
//           lane' = {v5,v6,v7,v0,v8} at bits {0,1,2,3,4}  (qubit 8 at lane bit 3)
__host__ __device__ constexpr int jB(int v) {
    int kp = (v >> 1) & 15;
    int lp = ((v >> 5) & 1) | (((v >> 6) & 1) << 1) | (((v >> 7) & 1) << 2)
           | ((v & 1) << 3) | (((v >> 8) & 1) << 4);
    return (kp << 5) | lp;
}
__host__ __device__ constexpr int vB(int kp, int ln) {   // inverse of jB
    return ((ln >> 3) & 1) | (kp << 1) | ((ln & 1) << 5)
         | (((ln >> 1) & 1) << 6) | (((ln >> 2) & 1) << 7) | (((ln >> 4) & 1) << 8);
}
// measurement constants for layout B (acc[w] uses t = 8-w)
__host__ __device__ constexpr int kidx_w(int w) { return (mask_bit(8 - w) >> 1) & 15; }
__host__ __device__ constexpr int lmk_w(int w) {
    int mk = mask_bit(8 - w);
    return ((mk >> 5) & 1) | (((mk >> 6) & 1) << 1) | (((mk >> 7) & 1) << 2)
         | ((mk & 1) << 3) | (((mk >> 8) & 1) << 4);
}

__device__ __forceinline__ int swz(int i) { return i ^ ((i >> 5) & 15); }

// ---- RY gates (real coefficients) ----
template <int PB>
__device__ __forceinline__ void ry_reg(u64 (&R)[8], u64 (&I)[8], float c, float s) {
    const u64 pc = pk(c, c), ps = pk(s, s), ns = pk(-s, -s);
    const int d = 1 << PB;
#pragma unroll
    for (int t = 0; t < 4; t++) {
        const int q = ((t >> PB) << (PB + 1)) | (t & (d - 1));
        const int j = q | d;
        u64 Rq = R[q], Iq = I[q], Rj = R[j], Ij = I[j];
        R[q] = f2fma(pc, Rq, f2mul(ns, Rj));
        I[q] = f2fma(pc, Iq, f2mul(ns, Ij));
        R[j] = f2fma(ps, Rq, f2mul(pc, Rj));
        I[j] = f2fma(ps, Iq, f2mul(pc, Ij));
    }
}
__device__ __forceinline__ void ry_in(u64 (&R)[8], u64 (&I)[8], float c, float s) {
    const u64 pc = pk(c, c), cs2 = pk(-s, s);
#pragma unroll
    for (int p = 0; p < 8; p++) {
        R[p] = f2fma(pc, R[p], f2mul(cs2, swp(R[p])));
        I[p] = f2fma(pc, I[p], f2mul(cs2, swp(I[p])));
    }
}
template <int P>
__device__ __forceinline__ void ry_cross(u64 (&R)[8], u64 (&I)[8],
                                         float c, float s, int lane) {
    const int msk = 1 << P;
    const float sp = (lane & msk) ? s : -s;
    const u64 pc = pk(c, c), psl = pk(sp, sp);
#pragma unroll
    for (int p = 0; p < 8; p++) {
        u64 shR = __shfl_xor_sync(FULL_MASK, R[p], msk);
        u64 shI = __shfl_xor_sync(FULL_MASK, I[p], msk);
        R[p] = f2fma(pc, R[p], f2mul(psl, shR));
        I[p] = f2fma(pc, I[p], f2mul(psl, shI));
    }
}

// ---- precomputed 512-entry diagonal (pack-major packed tables) ----
__device__ __forceinline__ void apply_diag(u64 (&R)[8], u64 (&I)[8],
                                           const float* Tr, const float* Ti,
                                           int lane) {
    const u64* cr = (const u64*)Tr;
    const u64* ci = (const u64*)Ti;
#pragma unroll
    for (int p = 0; p < 8; p++) {
        u64 Cr = cr[p * 32 + lane], Ci = ci[p * 32 + lane];
        u64 Rn = f2fma(R[p], Cr, f2mul(f2neg(I[p]), Ci));
        I[p]   = f2fma(R[p], Ci, f2mul(I[p], Cr));
        R[p] = Rn;
    }
}

// ---- scatter (table) then identity gather through the warp's shared buffer ----
__device__ __forceinline__ void scat_gath(u64 (&R)[8], u64 (&I)[8],
                                          float2* buf, const ushort2* pm, int lane) {
    __syncwarp();
#pragma unroll
    for (int p = 0; p < 8; p++) {
        float r0, r1, i0f, i1f;
        up(R[p], r0, r1); up(I[p], i0f, i1f);
        ushort2 d = pm[p * 32 + lane];
        buf[d.x] = make_float2(r0, i0f);
        buf[d.y] = make_float2(r1, i1f);
    }
    __syncwarp();
#pragma unroll
    for (int p = 0; p < 8; p++) {
        float2 v0 = buf[swz(p * 64 + lane)];
        float2 v1 = buf[swz(p * 64 + 32 + lane)];
        R[p] = pk(v0.x, v1.x);
        I[p] = pk(v0.y, v1.y);
    }
}

__global__ void __launch_bounds__(256)
qsim_kernel(const float* __restrict__ x, const float* __restrict__ wt,
            float* __restrict__ out, int B) {
    __shared__ float2 s_m00[9], s_m01[9];        // layer-0 Rot (for init fold)
    __shared__ float2 s_ry[18];                  // (c, s) layers 1,2
    __shared__ float2 s_ph[3][9];                // e^{-i ang/2}: phi1, omega1, phi2
    __shared__ ushort2 s_pC0[256];               // C0 scatter (A->A)
    __shared__ ushort2 s_pAB[256];               // A->B transpose scatter
    __shared__ ushort2 s_pC1B[256];              // C1 scatter from B positions -> A
    __shared__ float s_T1r[512], s_T1i[512];     // D1(layer1), layout A
    __shared__ float s_TEr[512], s_TEi[512];     // D2(l1)*C1-conj(D1(l2)), layout B
    __shared__ float2 s_buf[8][512];

    const int tid = threadIdx.x;

    // ---- per-layer gate data ----
    if (tid < 27) {
        const int l = tid / 9, w = tid % 9;
        const float* p = wt + tid * 3;
        float phi = p[0], th = p[1], om = p[2];
        float c, s;
        __sincosf(0.5f * th, &s, &c);
        if (l == 0) {
            float a  = 0.5f * (phi + om);
            float bb = 0.5f * (phi - om);
            float ca, sa, cb, sb;
            __sincosf(a, &sa, &ca);
            __sincosf(bb, &sb, &cb);
            s_m00[w] = make_float2(c * ca, -c * sa);
            s_m01[w] = make_float2(-s * cb, -s * sb);
        } else {
            s_ry[(l - 1) * 9 + w] = make_float2(c, s);
            float cp, sp;
            __sincosf(0.5f * phi, &sp, &cp);
            if (l == 1) {
                s_ph[0][w] = make_float2(cp, -sp);
                float co, so;
                __sincosf(0.5f * om, &so, &co);
                s_ph[1][w] = make_float2(co, -so);
            } else {
                s_ph[2][w] = make_float2(cp, -sp);
            }
        }
    }
    // ---- scatter tables ----
    for (int e = tid; e < 256; e += blockDim.x) {
        int p = e >> 5, ln = e & 31;
        int i0 = p * 64 + ln, i1 = i0 + 32;
        s_pC0[e]  = make_ushort2((unsigned short)swz(perm_apply(1, i0)),
                                 (unsigned short)swz(perm_apply(1, i1)));
        s_pAB[e]  = make_ushort2((unsigned short)swz(jB(i0)),
                                 (unsigned short)swz(jB(i1)));
        int v0 = vB(2 * p, ln), v1 = vB(2 * p + 1, ln);
        s_pC1B[e] = make_ushort2((unsigned short)swz(perm_apply(2, v0)),
                                 (unsigned short)swz(perm_apply(2, v1)));
    }
    __syncthreads();

    // ---- build diagonal tables (weights-only; once per block) ----
    for (int i = tid; i < 512; i += blockDim.x) {
        float t1r = 1.0f, t1i = 0.0f, ter = 1.0f, tei = 0.0f;
        int ci = perm_apply(2, i);
#pragma unroll
        for (int w = 0; w < 9; w++) {
            int b0 = (i >> (8 - w)) & 1;
            int b1 = (ci >> (8 - w)) & 1;
            float2 p0 = s_ph[0][w];
            float y0 = b0 ? -p0.y : p0.y;
            float nr = t1r * p0.x - t1i * y0;
            t1i = t1r * y0 + t1i * p0.x; t1r = nr;
            float2 p1 = s_ph[1][w];
            float y1 = b0 ? -p1.y : p1.y;
            nr = ter * p1.x - tei * y1;
            tei = ter * y1 + tei * p1.x; ter = nr;
            float2 p2 = s_ph[2][w];
            float y2 = b1 ? -p2.y : p2.y;
            nr = ter * p2.x - tei * y2;
            tei = ter * y2 + tei * p2.x; ter = nr;
        }
        // T1 slot: layout A
        {
            int k = i >> 5, ln = i & 31;
            int fi = ((k >> 1) * 32 + ln) * 2 + (k & 1);
            s_T1r[fi] = t1r; s_T1i[fi] = t1i;
        }
        // TE slot: layout B
        {
            int j = jB(i);
            int kp = j >> 5, ln = j & 31;
            int fi = ((kp >> 1) * 32 + ln) * 2 + (kp & 1);
            s_TEr[fi] = ter; s_TEi[fi] = tei;
        }
    }
    __syncthreads();

    const int lane = tid & 31;
    const int warp = tid >> 5;
    float2* buf = s_buf[warp];
    const int gw = blockIdx.x * (blockDim.x >> 5) + warp;
    const int nw = gridDim.x * (blockDim.x >> 5);

    for (int b = gw; b < B; b += nw) {
        // ---- per-qubit angles ----
        float cs[9], sn[9];
#pragma unroll
        for (int w = 0; w < 9; w++) {
            float h2 = 0.5f * __ldg(&x[b * 9 + w]);
            __sincosf(h2, &sn[w], &cs[w]);
        }

        // ---- layer-0 rotations folded into per-qubit 2-vectors ----
        float Lr = 1.0f, Li = 0.0f;
#pragma unroll
        for (int p = 0; p < 5; p++) {
            int w = 8 - p;
            float2 m0 = s_m00[w], m1 = s_m01[w];
            float c = cs[w], s = sn[w];
            float vr, vi;
            if ((lane >> p) & 1) { vr = -m1.x * c - m0.y * s; vi = m1.y * c - m0.x * s; }
            else                 { vr =  m0.x * c + m1.y * s; vi = m0.y * c - m1.x * s; }
            float nr = Lr * vr - Li * vi;
            Li = Lr * vi + Li * vr;
            Lr = nr;
        }
        float awr[4], awi[4], bwr[4], bwi[4];
#pragma unroll
        for (int w = 0; w < 4; w++) {
            float2 m0 = s_m00[w], m1 = s_m01[w];
            float c = cs[w], s = sn[w];
            awr[w] =  m0.x * c + m1.y * s;  awi[w] = m0.y * c - m1.x * s;
            bwr[w] = -m1.x * c - m0.y * s;  bwi[w] = m1.y * c - m0.x * s;
        }
        float A0r = awr[0] * Lr - awi[0] * Li, A0i = awr[0] * Li + awi[0] * Lr;
        float B0r = bwr[0] * Lr - bwi[0] * Li, B0i = bwr[0] * Li + bwi[0] * Lr;

        // ---- build state by packed doubling over k bits ----
        u64 R[8], I[8];
        R[0] = pk(awr[3], bwr[3]); I[0] = pk(awi[3], bwi[3]);
        cmulp(R[1], I[1], R[0], I[0], bwr[2], bwi[2]);
        cmulp(R[0], I[0], R[0], I[0], awr[2], awi[2]);
        cmulp(R[2], I[2], R[0], I[0], bwr[1], bwi[1]);
        cmulp(R[3], I[3], R[1], I[1], bwr[1], bwi[1]);
        cmulp(R[0], I[0], R[0], I[0], awr[1], awi[1]);
        cmulp(R[1], I[1], R[1], I[1], awr[1], awi[1]);
#pragma unroll
        for (int p = 0; p < 4; p++)
            cmulp(R[p + 4], I[p + 4], R[p], I[p], B0r, B0i);
#pragma unroll
        for (int p = 0; p < 4; p++)
            cmulp(R[p], I[p], R[p], I[p], A0r, A0i);

        // ---- C0 permutation (A -> A) ----
        scat_gath(R, I, buf, s_pC0, lane);

        // ---- D1(layer1) diag (A) ----
        apply_diag(R, I, s_T1r, s_T1i, lane);

        // ---- layer 1, A-phase gates: qubits 0..3 ----
        ry_reg<2>(R, I, s_ry[0].x, s_ry[0].y);
        ry_reg<1>(R, I, s_ry[1].x, s_ry[1].y);
        ry_reg<0>(R, I, s_ry[2].x, s_ry[2].y);
        ry_in    (R, I, s_ry[3].x, s_ry[3].y);

        // ---- transpose A -> B ----
        scat_gath(R, I, buf, s_pAB, lane);

        // ---- layer 1, B-phase gates: qubits 4..7 in regs, qubit 8 cross ----
        ry_reg<2>(R, I, s_ry[4].x, s_ry[4].y);
        ry_reg<1>(R, I, s_ry[5].x, s_ry[5].y);
        ry_reg<0>(R, I, s_ry[6].x, s_ry[6].y);
        ry_in    (R, I, s_ry[7].x, s_ry[7].y);
        ry_cross<3>(R, I, s_ry[8].x, s_ry[8].y, lane);

        // ---- E diag (B) ----
        apply_diag(R, I, s_TEr, s_TEi, lane);

        // ---- C1 permutation composed with B -> A transpose ----
        scat_gath(R, I, buf, s_pC1B, lane);

        // ---- layer 2, A-phase gates ----
        ry_reg<2>(R, I, s_ry[9].x,  s_ry[9].y);
        ry_reg<1>(R, I, s_ry[10].x, s_ry[10].y);
        ry_reg<0>(R, I, s_ry[11].x, s_ry[11].y);
        ry_in    (R, I, s_ry[12].x, s_ry[12].y);

        // ---- transpose A -> B ----
        scat_gath(R, I, buf, s_pAB, lane);

        // ---- layer 2, B-phase gates ----
        ry_reg<2>(R, I, s_ry[13].x, s_ry[13].y);
        ry_reg<1>(R, I, s_ry[14].x, s_ry[14].y);
        ry_reg<0>(R, I, s_ry[15].x, s_ry[15].y);
        ry_in    (R, I, s_ry[16].x, s_ry[16].y);
        ry_cross<3>(R, I, s_ry[17].x, s_ry[17].y, lane);

        // ---- measurement in layout B (final CNOT folded as parity masks) ----
        u64 P[8];
        const u64 NEG1 = pk(-1.0f, -1.0f);
#pragma unroll
        for (int p = 0; p < 8; p++)
            P[p] = f2fma(R[p], R[p], f2mul(I[p], I[p]));
#pragma unroll
        for (int j = 0; j < 3; j++) {
            const int d = 1 << j;
#pragma unroll
            for (int t = 0; t < 4; t++) {
                const int q = ((t >> j) << (j + 1)) | (t & (d - 1));
                const int v = q | d;
                u64 a = P[q], bb = P[v];
                P[q] = f2add(a, bb);
                P[v] = f2fma(bb, NEG1, a);
            }
        }
        float S[16];
#pragma unroll
        for (int p = 0; p < 8; p++) {
            float lo, hi; up(P[p], lo, hi);
            S[2 * p]     = lo + hi;
            S[2 * p + 1] = lo - hi;
        }
        constexpr int KW[9] = { kidx_w(0), kidx_w(1), kidx_w(2), kidx_w(3),
                                kidx_w(4), kidx_w(5), kidx_w(6), kidx_w(7), kidx_w(8) };
        constexpr int LW[9] = { lmk_w(0), lmk_w(1), lmk_w(2), lmk_w(3),
                                lmk_w(4), lmk_w(5), lmk_w(6), lmk_w(7), lmk_w(8) };
        float acc[9];
#pragma unroll
        for (int w = 0; w < 9; w++) {
            float v = S[KW[w]];
            acc[w] = (__popc(lane & LW[w]) & 1) ? -v : v;
        }
        // packed warp reduction
        u64 ac[4];
#pragma unroll
        for (int j = 0; j < 4; j++) ac[j] = pk(acc[2 * j], acc[2 * j + 1]);
        float a8 = acc[8];
#pragma unroll
        for (int off = 16; off > 0; off >>= 1) {
#pragma unroll
            for (int j = 0; j < 4; j++)
                ac[j] = f2add(ac[j], __shfl_xor_sync(FULL_MASK, ac[j], off));
            a8 += __shfl_xor_sync(FULL_MASK, a8, off);
        }
        if (lane == 0) {
#pragma unroll
            for (int j = 0; j < 4; j++) {
                float lo, hi; up(ac[j], lo, hi);
                out[b * 9 + 2 * j]     = lo;
                out[b * 9 + 2 * j + 1] = hi;
            }
            out[b * 9 + 8] = a8;
        }
    }
}

extern "C" void kernel_launch(void* const* d_in, const int* in_sizes, int n_in,
                              void* d_out, int out_size) {
    const float* x  = (const float*)d_in[0];   // (32768, 9) fp32
    const float* wt = (const float*)d_in[1];   // (3, 9, 3) fp32
    float* out = (float*)d_out;                // (32768, 9) fp32
    int B = in_sizes[0] / 9;
    qsim_kernel<<<2048, 256>>>(x, wt, out, B);
}

// round 16
// speedup vs baseline: 1.9947x; 1.0231x over previous
#include <cuda_runtime.h>

#define FULL_MASK 0xffffffffu
typedef unsigned long long u64;

// ---- f32x2 packed helpers (sm_103a FFMA2/FADD2 only reachable via PTX) ----
__device__ __forceinline__ u64 pk(float lo, float hi) {
    u64 r; asm("mov.b64 %0,{%1,%2};" : "=l"(r) : "f"(lo), "f"(hi)); return r;
}
__device__ __forceinline__ void up(u64 v, float& lo, float& hi) {
    asm("mov.b64 {%0,%1},%2;" : "=f"(lo), "=f"(hi) : "l"(v));
}
__device__ __forceinline__ u64 f2fma(u64 a, u64 b, u64 c) {
    u64 d; asm("fma.rn.f32x2 %0,%1,%2,%3;" : "=l"(d) : "l"(a), "l"(b), "l"(c)); return d;
}
__device__ __forceinline__ u64 f2mul(u64 a, u64 b) {
    u64 d; asm("mul.rn.f32x2 %0,%1,%2;" : "=l"(d) : "l"(a), "l"(b)); return d;
}
__device__ __forceinline__ u64 f2add(u64 a, u64 b) {
    u64 d; asm("add.rn.f32x2 %0,%1,%2;" : "=l"(d) : "l"(a), "l"(b)); return d;
}
__device__ __forceinline__ u64 swp(u64 v) {
    float a, b; up(v, a, b); return pk(b, a);
}

// packed complex multiply by broadcast scalar (yr,yi): dst = src * y  (split R/I)
__device__ __forceinline__ void cmulp(u64& Rd, u64& Id, u64 Rs, u64 Is,
                                      float yr, float yi) {
    u64 pyr = pk(yr, yr), pyi = pk(yi, yi), nyi = pk(-yi, -yi);
    Rd = f2fma(Rs, pyr, f2mul(Is, nyi));
    Id = f2fma(Rs, pyi, f2mul(Is, pyr));
}

// ---- compile-time CNOT-ring permutations & layout maps ----
__host__ __device__ constexpr int perm_apply(int r, int v) {
    for (int g = 0; g < 9; g++) {
        int t = g + r; if (t >= 9) t -= 9;
        v ^= ((v >> (8 - g)) & 1) << (8 - t);
    }
    return v;
}
__host__ __device__ constexpr int mask_bit(int t) {
    int m = 0;
    for (int b = 0; b < 9; b++)
        if ((perm_apply(3, 1 << b) >> t) & 1) m |= (1 << b);
    return m;
}
// Layout A: i = v (lane = v bits 0..4 = qubits 8..4; k = v bits 5..8 = qubits 3..0)
// Layout B: k' = v bits 1..4 (qubits 7..4); lane' = {v5,v6,v7,v0,v8} at bits {0..4}
__host__ __device__ constexpr int jB(int v) {
    int kp = (v >> 1) & 15;
    int lp = ((v >> 5) & 1) | (((v >> 6) & 1) << 1) | (((v >> 7) & 1) << 2)
           | ((v & 1) << 3) | (((v >> 8) & 1) << 4);
    return (kp << 5) | lp;
}
__host__ __device__ constexpr int vB(int kp, int ln) {   // inverse of jB
    return ((ln >> 3) & 1) | (kp << 1) | ((ln & 1) << 5)
         | (((ln >> 1) & 1) << 6) | (((ln >> 2) & 1) << 7) | (((ln >> 4) & 1) << 8);
}
// measurement constants for layout B (acc[w] uses t = 8-w)
__host__ __device__ constexpr int kidx_w(int w) { return (mask_bit(8 - w) >> 1) & 15; }
__host__ __device__ constexpr int lmk_w(int w) {
    int mk = mask_bit(8 - w);
    return ((mk >> 5) & 1) | (((mk >> 6) & 1) << 1) | (((mk >> 7) & 1) << 2)
         | ((mk & 1) << 3) | (((mk >> 8) & 1) << 4);
}

__device__ __forceinline__ int swz(int i) { return i ^ ((i >> 5) & 15); }

// ---- native-layout RY gates: amp k = V[k] = (re, im); real coeffs act componentwise ----
template <int PB>
__device__ __forceinline__ void ry16(u64 (&V)[16], float c, float s) {
    const u64 pc = pk(c, c), ps = pk(s, s), ns = pk(-s, -s);
    const int d = 1 << PB;
#pragma unroll
    for (int t = 0; t < 8; t++) {
        const int q = ((t >> PB) << (PB + 1)) | (t & (d - 1));
        const int j = q | d;
        u64 a = V[q], b = V[j];
        V[q] = f2fma(pc, a, f2mul(ns, b));
        V[j] = f2fma(ps, a, f2mul(pc, b));
    }
}
template <int P>
__device__ __forceinline__ void ry16_cross(u64 (&V)[16], float c, float s, int lane) {
    const int msk = 1 << P;
    const float sp = (lane & msk) ? s : -s;
    const u64 pc = pk(c, c), psl = pk(sp, sp);
#pragma unroll
    for (int k = 0; k < 16; k++) {
        u64 sh = __shfl_xor_sync(FULL_MASK, V[k], msk);
        V[k] = f2fma(pc, V[k], f2mul(psl, sh));
    }
}
// diag: per-amp float4 (cr, cr, -ci, ci); both halves are aligned pairs (free)
__device__ __forceinline__ void diag16(u64 (&V)[16], const float4* T, int lane) {
#pragma unroll
    for (int k = 0; k < 16; k++) {
        float4 t = T[k * 32 + lane];
        u64 ccc = pk(t.x, t.y);
        u64 cnc = pk(t.z, t.w);
        V[k] = f2fma(V[k], ccc, f2mul(swp(V[k]), cnc));
    }
}
// native scatter (table) / identity gather — raw 64-bit moves, no repacking
__device__ __forceinline__ void scat_gath16(u64 (&V)[16], float2* buf,
                                            const ushort2* pm, int lane) {
    __syncwarp();
#pragma unroll
    for (int p = 0; p < 8; p++) {
        ushort2 d = pm[p * 32 + lane];
        *(u64*)&buf[d.x] = V[2 * p];
        *(u64*)&buf[d.y] = V[2 * p + 1];
    }
    __syncwarp();
#pragma unroll
    for (int k = 0; k < 16; k++)
        V[k] = *(const u64*)&buf[swz(k * 32 + lane)];
}

__global__ void __launch_bounds__(256)
qsim_kernel(const float* __restrict__ x, const float* __restrict__ wt,
            float* __restrict__ out, int B) {
    __shared__ float2 s_m00[9], s_m01[9];        // layer-0 Rot (for init fold)
    __shared__ float2 s_ry[18];                  // (c, s) layers 1,2
    __shared__ float2 s_ph[3][9];                // e^{-i ang/2}: phi1, omega1, phi2
    __shared__ ushort2 s_pC0[256];               // C0 scatter (A->A)
    __shared__ ushort2 s_pAB[256];               // A->B transpose scatter
    __shared__ ushort2 s_pC1B[256];              // C1 scatter from B positions -> A
    __shared__ float4 s_T14[512];                // D1(layer1), layout A, (cr,cr,-ci,ci)
    __shared__ float4 s_TE4[512];                // D2(l1)*C1-conj(D1(l2)), layout B
    __shared__ float2 s_buf[8][512];

    const int tid = threadIdx.x;

    // ---- per-layer gate data ----
    if (tid < 27) {
        const int l = tid / 9, w = tid % 9;
        const float* p = wt + tid * 3;
        float phi = p[0], th = p[1], om = p[2];
        float c, s;
        __sincosf(0.5f * th, &s, &c);
        if (l == 0) {
            float a  = 0.5f * (phi + om);
            float bb = 0.5f * (phi - om);
            float ca, sa, cb, sb;
            __sincosf(a, &sa, &ca);
            __sincosf(bb, &sb, &cb);
            s_m00[w] = make_float2(c * ca, -c * sa);
            s_m01[w] = make_float2(-s * cb, -s * sb);
        } else {
            s_ry[(l - 1) * 9 + w] = make_float2(c, s);
            float cp, sp;
            __sincosf(0.5f * phi, &sp, &cp);
            if (l == 1) {
                s_ph[0][w] = make_float2(cp, -sp);
                float co, so;
                __sincosf(0.5f * om, &so, &co);
                s_ph[1][w] = make_float2(co, -so);
            } else {
                s_ph[2][w] = make_float2(cp, -sp);
            }
        }
    }
    // ---- scatter tables ----
    for (int e = tid; e < 256; e += blockDim.x) {
        int p = e >> 5, ln = e & 31;
        int i0 = p * 64 + ln, i1 = i0 + 32;
        s_pC0[e]  = make_ushort2((unsigned short)swz(perm_apply(1, i0)),
                                 (unsigned short)swz(perm_apply(1, i1)));
        s_pAB[e]  = make_ushort2((unsigned short)swz(jB(i0)),
                                 (unsigned short)swz(jB(i1)));
        int v0 = vB(2 * p, ln), v1 = vB(2 * p + 1, ln);
        s_pC1B[e] = make_ushort2((unsigned short)swz(perm_apply(2, v0)),
                                 (unsigned short)swz(perm_apply(2, v1)));
    }
    __syncthreads();

    // ---- build diagonal tables (weights-only; once per block) ----
    for (int i = tid; i < 512; i += blockDim.x) {
        float t1r = 1.0f, t1i = 0.0f, ter = 1.0f, tei = 0.0f;
        int ci = perm_apply(2, i);
#pragma unroll
        for (int w = 0; w < 9; w++) {
            int b0 = (i >> (8 - w)) & 1;
            int b1 = (ci >> (8 - w)) & 1;
            float2 p0 = s_ph[0][w];
            float y0 = b0 ? -p0.y : p0.y;
            float nr = t1r * p0.x - t1i * y0;
            t1i = t1r * y0 + t1i * p0.x; t1r = nr;
            float2 p1 = s_ph[1][w];
            float y1 = b0 ? -p1.y : p1.y;
            nr = ter * p1.x - tei * y1;
            tei = ter * y1 + tei * p1.x; ter = nr;
            float2 p2 = s_ph[2][w];
            float y2 = b1 ? -p2.y : p2.y;
            nr = ter * p2.x - tei * y2;
            tei = ter * y2 + tei * p2.x; ter = nr;
        }
        s_T14[i] = make_float4(t1r, t1r, -t1i, t1i);          // layout A slot = i
        s_TE4[jB(i)] = make_float4(ter, ter, -tei, tei);      // layout B slot
    }
    __syncthreads();

    const int lane = tid & 31;
    const int warp = tid >> 5;
    float2* buf = s_buf[warp];
    const int gw = blockIdx.x * (blockDim.x >> 5) + warp;
    const int nw = gridDim.x * (blockDim.x >> 5);

    // measurement constants (lane-only; hoisted out of the batch loop)
    constexpr int KW[9] = { kidx_w(0), kidx_w(1), kidx_w(2), kidx_w(3),
                            kidx_w(4), kidx_w(5), kidx_w(6), kidx_w(7), kidx_w(8) };
    constexpr int LW[9] = { lmk_w(0), lmk_w(1), lmk_w(2), lmk_w(3),
                            lmk_w(4), lmk_w(5), lmk_w(6), lmk_w(7), lmk_w(8) };
    float sg[9];
#pragma unroll
    for (int w = 0; w < 9; w++)
        sg[w] = (__popc(lane & LW[w]) & 1) ? -1.0f : 1.0f;

    for (int b = gw; b < B; b += nw) {
        // ---- per-qubit angles ----
        float cs[9], sn[9];
#pragma unroll
        for (int w = 0; w < 9; w++) {
            float h2 = 0.5f * __ldg(&x[b * 9 + w]);
            __sincosf(h2, &sn[w], &cs[w]);
        }

        // ---- layer-0 rotations folded into per-qubit 2-vectors ----
        float Lr = 1.0f, Li = 0.0f;
#pragma unroll
        for (int p = 0; p < 5; p++) {
            int w = 8 - p;
            float2 m0 = s_m00[w], m1 = s_m01[w];
            float c = cs[w], s = sn[w];
            float vr, vi;
            if ((lane >> p) & 1) { vr = -m1.x * c - m0.y * s; vi = m1.y * c - m0.x * s; }
            else                 { vr =  m0.x * c + m1.y * s; vi = m0.y * c - m1.x * s; }
            float nr = Lr * vr - Li * vi;
            Li = Lr * vi + Li * vr;
            Lr = nr;
        }
        float awr[4], awi[4], bwr[4], bwi[4];
#pragma unroll
        for (int w = 0; w < 4; w++) {
            float2 m0 = s_m00[w], m1 = s_m01[w];
            float c = cs[w], s = sn[w];
            awr[w] =  m0.x * c + m1.y * s;  awi[w] = m0.y * c - m1.x * s;
            bwr[w] = -m1.x * c - m0.y * s;  bwi[w] = m1.y * c - m0.x * s;
        }
        float A0r = awr[0] * Lr - awi[0] * Li, A0i = awr[0] * Li + awi[0] * Lr;
        float B0r = bwr[0] * Lr - bwi[0] * Li, B0i = bwr[0] * Li + bwi[0] * Lr;

        // ---- build state by packed doubling over k bits (split R/I packs) ----
        u64 R[8], I[8];
        R[0] = pk(awr[3], bwr[3]); I[0] = pk(awi[3], bwi[3]);
        cmulp(R[1], I[1], R[0], I[0], bwr[2], bwi[2]);
        cmulp(R[0], I[0], R[0], I[0], awr[2], awi[2]);
        cmulp(R[2], I[2], R[0], I[0], bwr[1], bwi[1]);
        cmulp(R[3], I[3], R[1], I[1], bwr[1], bwi[1]);
        cmulp(R[0], I[0], R[0], I[0], awr[1], awi[1]);
        cmulp(R[1], I[1], R[1], I[1], awr[1], awi[1]);
#pragma unroll
        for (int p = 0; p < 4; p++)
            cmulp(R[p + 4], I[p + 4], R[p], I[p], B0r, B0i);
#pragma unroll
        for (int p = 0; p < 4; p++)
            cmulp(R[p], I[p], R[p], I[p], A0r, A0i);

        // ---- C0 permutation: scatter split packs, gather native amps ----
        u64 V[16];
        {
            __syncwarp();
#pragma unroll
            for (int p = 0; p < 8; p++) {
                float r0, r1, i0f, i1f;
                up(R[p], r0, r1); up(I[p], i0f, i1f);
                ushort2 d = s_pC0[p * 32 + lane];
                buf[d.x] = make_float2(r0, i0f);
                buf[d.y] = make_float2(r1, i1f);
            }
            __syncwarp();
#pragma unroll
            for (int k = 0; k < 16; k++)
                V[k] = *(const u64*)&buf[swz(k * 32 + lane)];
        }

        // ---- D1(layer1) diag (A) ----
        diag16(V, s_T14, lane);

        // ---- layer 1, A-phase gates: qubits 0..3 (k bits 3..0) ----
        ry16<3>(V, s_ry[0].x, s_ry[0].y);
        ry16<2>(V, s_ry[1].x, s_ry[1].y);
        ry16<1>(V, s_ry[2].x, s_ry[2].y);
        ry16<0>(V, s_ry[3].x, s_ry[3].y);

        // ---- transpose A -> B ----
        scat_gath16(V, buf, s_pAB, lane);

        // ---- layer 1, B-phase: qubits 4..7 (k' bits 3..0) + qubit 8 cross ----
        ry16<3>(V, s_ry[4].x, s_ry[4].y);
        ry16<2>(V, s_ry[5].x, s_ry[5].y);
        ry16<1>(V, s_ry[6].x, s_ry[6].y);
        ry16<0>(V, s_ry[7].x, s_ry[7].y);
        ry16_cross<3>(V, s_ry[8].x, s_ry[8].y, lane);

        // ---- E diag (B) ----
        diag16(V, s_TE4, lane);

        // ---- C1 permutation composed with B -> A transpose ----
        scat_gath16(V, buf, s_pC1B, lane);

        // ---- layer 2, A-phase gates ----
        ry16<3>(V, s_ry[9].x,  s_ry[9].y);
        ry16<2>(V, s_ry[10].x, s_ry[10].y);
        ry16<1>(V, s_ry[11].x, s_ry[11].y);
        ry16<0>(V, s_ry[12].x, s_ry[12].y);

        // ---- transpose A -> B ----
        scat_gath16(V, buf, s_pAB, lane);

        // ---- layer 2, B-phase gates ----
        ry16<3>(V, s_ry[13].x, s_ry[13].y);
        ry16<2>(V, s_ry[14].x, s_ry[14].y);
        ry16<1>(V, s_ry[15].x, s_ry[15].y);
        ry16<0>(V, s_ry[16].x, s_ry[16].y);
        ry16_cross<3>(V, s_ry[17].x, s_ry[17].y, lane);

        // ---- measurement in layout B (final CNOT folded as parity masks) ----
        u64 M[16];
        const u64 NEG1 = pk(-1.0f, -1.0f);
#pragma unroll
        for (int k = 0; k < 16; k++)
            M[k] = f2mul(V[k], V[k]);                  // (re^2, im^2)
        // full packed WHT over the 4 k'-bits (componentwise; linear)
#pragma unroll
        for (int j = 0; j < 4; j++) {
            const int d = 1 << j;
#pragma unroll
            for (int t = 0; t < 8; t++) {
                const int q = ((t >> j) << (j + 1)) | (t & (d - 1));
                const int v = q | d;
                u64 a = M[q], bb = M[v];
                M[q] = f2add(a, bb);
                M[v] = f2fma(bb, NEG1, a);
            }
        }
        float acc[9];
#pragma unroll
        for (int w = 0; w < 9; w++) {
            float lo, hi; up(M[KW[w]], lo, hi);
            acc[w] = (lo + hi) * sg[w];
        }
        // packed warp reduction
        u64 ac[4];
#pragma unroll
        for (int j = 0; j < 4; j++) ac[j] = pk(acc[2 * j], acc[2 * j + 1]);
        float a8 = acc[8];
#pragma unroll
        for (int off = 16; off > 0; off >>= 1) {
#pragma unroll
            for (int j = 0; j < 4; j++)
                ac[j] = f2add(ac[j], __shfl_xor_sync(FULL_MASK, ac[j], off));
            a8 += __shfl_xor_sync(FULL_MASK, a8, off);
        }
        if (lane == 0) {
#pragma unroll
            for (int j = 0; j < 4; j++) {
                float lo, hi; up(ac[j], lo, hi);
                out[b * 9 + 2 * j]     = lo;
                out[b * 9 + 2 * j + 1] = hi;
            }
            out[b * 9 + 8] = a8;
        }
    }
}

extern "C" void kernel_launch(void* const* d_in, const int* in_sizes, int n_in,
                              void* d_out, int out_size) {
    const float* x  = (const float*)d_in[0];   // (32768, 9) fp32
    const float* wt = (const float*)d_in[1];   // (3, 9, 3) fp32
    float* out = (float*)d_out;                // (32768, 9) fp32
    int B = in_sizes[0] / 9;
    qsim_kernel<<<2048, 256>>>(x, wt, out, B);
}